// round 4
// baseline (speedup 1.0000x reference)
#include <cuda_runtime.h>
#include <cuda_bf16.h>
#include <cstddef>

// ---------------- Problem constants ----------------
#define TT 4
#define BB 32
#define CC 384
#define NN 196            // H*W = 14*14
#define GG (TT*BB)        // 128 fused (t,b) batches
#define C3 (3*CC)         // 1152
#define HEADS 8
#define DH 48             // C/HEADS

// ---------------- Scratch (device globals; no allocs allowed) ----------------
__device__ float g_Wcat [C3*CC];            // [1152][384] concat wq;wk;wv
__device__ float g_scale[C3];
__device__ float g_bias [C3];
__device__ float g_Yqkv [(size_t)GG*C3*NN]; // pre-activation QKV   115.6MB
__device__ float g_Sqkv [(size_t)GG*C3*NN]; // QKV spikes           115.6MB
__device__ float g_Yattn[(size_t)GG*CC*NN]; // attn pre-LIF          38.5MB
__device__ float g_Sattn[(size_t)GG*CC*NN]; // attn spikes           38.5MB
__device__ float g_Y2   [(size_t)GG*CC*NN]; // proj pre-LIF          38.5MB

// ---------------- Prep: concatenate weights / scales / biases ----------------
__global__ void prep_kernel(const float* __restrict__ wq, const float* __restrict__ wk,
                            const float* __restrict__ wv,
                            const float* __restrict__ sq, const float* __restrict__ bq,
                            const float* __restrict__ sk, const float* __restrict__ bk,
                            const float* __restrict__ sv, const float* __restrict__ bv)
{
    int i = blockIdx.x * blockDim.x + threadIdx.x;
    const int W = CC*CC;
    if (i < W) {
        g_Wcat[i]       = wq[i];
        g_Wcat[W + i]   = wk[i];
        g_Wcat[2*W + i] = wv[i];
    }
    if (i < CC) {
        g_scale[i]        = sq[i];  g_bias[i]        = bq[i];
        g_scale[CC + i]   = sk[i];  g_bias[CC + i]   = bk[i];
        g_scale[2*CC + i] = sv[i];  g_bias[2*CC + i] = bv[i];
    }
}

// ---------------- Batched SGEMM: Y[g] = A(MxK) * B[g](KxN), epilogue *scale+bias ----
// M multiple of 128, K = 384, N = 196 (tiled exactly as 2x98 -> no bounds checks).
#define BM 128
#define BN 98
#define BK 16
#define TM 8
#define TN 7
#define GEMM_THREADS 224   // (BM/TM)*(BN/TN) = 16*14

__global__ __launch_bounds__(GEMM_THREADS)
void gemm_bn_kernel(const float* __restrict__ A,      // [M][384]
                    const float* __restrict__ Bbase,  // [G][384][196]
                    float* __restrict__ Ybase,        // [G][M][196]
                    const float* __restrict__ scale,
                    const float* __restrict__ bias,
                    int M)
{
    const int g  = blockIdx.z;
    const int m0 = blockIdx.y * BM;
    const int n0 = blockIdx.x * BN;
    const float* __restrict__ Bg = Bbase + (size_t)g * CC * NN;
    float* __restrict__ Yg       = Ybase + (size_t)g * M  * NN;

    __shared__ float As[BK][BM];
    __shared__ float Bs[BK][BN];

    const int tid  = threadIdx.x;
    const int tcol = tid % 14;     // 14 col-groups * TN(7) = 98
    const int trow = tid / 14;     // 16 row-groups * TM(8) = 128

    float acc[TM][TN];
    #pragma unroll
    for (int i = 0; i < TM; i++)
        #pragma unroll
        for (int j = 0; j < TN; j++) acc[i][j] = 0.f;

    for (int k0 = 0; k0 < CC; k0 += BK) {
        // A tile: [BM rows m][BK cols k], vectorized float4, stored transposed
        for (int i = tid; i < BM * (BK/4); i += GEMM_THREADS) {
            int r  = i / (BK/4);
            int cq = i % (BK/4);
            float4 v = *reinterpret_cast<const float4*>(&A[(size_t)(m0 + r) * CC + k0 + cq*4]);
            As[cq*4+0][r] = v.x; As[cq*4+1][r] = v.y;
            As[cq*4+2][r] = v.z; As[cq*4+3][r] = v.w;
        }
        // B tile: [BK rows k][BN cols n]
        for (int i = tid; i < BK * BN; i += GEMM_THREADS) {
            int kk = i / BN;
            int nn = i % BN;
            Bs[kk][nn] = Bg[(size_t)(k0 + kk) * NN + n0 + nn];
        }
        __syncthreads();

        #pragma unroll
        for (int kk = 0; kk < BK; kk++) {
            float af[TM], bf[TN];
            #pragma unroll
            for (int i = 0; i < TM; i++) af[i] = As[kk][trow*TM + i];
            #pragma unroll
            for (int j = 0; j < TN; j++) bf[j] = Bs[kk][tcol*TN + j];
            #pragma unroll
            for (int i = 0; i < TM; i++)
                #pragma unroll
                for (int j = 0; j < TN; j++)
                    acc[i][j] = fmaf(af[i], bf[j], acc[i][j]);
        }
        __syncthreads();
    }

    #pragma unroll
    for (int i = 0; i < TM; i++) {
        int d = m0 + trow*TM + i;
        float sc = scale[d], bi = bias[d];
        #pragma unroll
        for (int j = 0; j < TN; j++)
            Yg[(size_t)d * NN + n0 + tcol*TN + j] = acc[i][j] * sc + bi;
    }
}

// ---------------- Multi-step LIF (tau=2, hard reset to 0) ----------------
// Layout [T][per_t]; forward spike value is exactly the Heaviside output.
__global__ void lif_kernel(const float* __restrict__ Y, float* __restrict__ S,
                           int per_t, float vth)
{
    int idx = blockIdx.x * blockDim.x + threadIdx.x;
    if (idx >= per_t) return;
    float v = 0.f;
    #pragma unroll
    for (int t = 0; t < TT; t++) {
        float y = Y[(size_t)t * per_t + idx];
        v = v + (y - v) * 0.5f;                  // /TAU == *0.5 (exact)
        float s = (v >= vth) ? 1.f : 0.f;
        S[(size_t)t * per_t + idx] = s;
        v = v * (1.f - s);                       // hard reset
    }
}

// ---------------- Exact factored spiking attention ----------------
// out = (q @ (k^T v)) * 0.125 ; all inputs binary -> exact integer fp32 math.
// One block per (g, head). Spike slices are [48][196] rows of g_Sqkv.
__global__ __launch_bounds__(256)
void attn_kernel(const float* __restrict__ S, float* __restrict__ Yattn)
{
    extern __shared__ float sm[];
    float* sq = sm;                 // 48*196
    float* sk = sq + DH*NN;
    float* sv = sk + DH*NN;
    float* Mm = sv + DH*NN;         // [48][48] : M[d1*48+d2]

    const int g = blockIdx.x >> 3;
    const int h = blockIdx.x & 7;
    const float* base = S + (size_t)g * C3 * NN;
    const float* gq = base + (size_t)(        h*DH) * NN;
    const float* gk = base + (size_t)(CC   +  h*DH) * NN;
    const float* gv = base + (size_t)(2*CC +  h*DH) * NN;
    const int tid = threadIdx.x;

    for (int i = tid; i < DH*NN; i += 256) { sq[i] = gq[i]; sk[i] = gk[i]; sv[i] = gv[i]; }
    __syncthreads();

    // Phase 1: M[d1][d2] = sum_m k[m][d1] * v[m][d2]   (48x48, K=196)
    for (int e = tid; e < DH*DH; e += 256) {
        int d1 = e / DH, d2 = e % DH;
        const float* kr = sk + d1*NN;
        const float* vr = sv + d2*NN;
        float a = 0.f;
        #pragma unroll 4
        for (int m = 0; m < NN; m++) a = fmaf(kr[m], vr[m], a);
        Mm[e] = a;
    }
    __syncthreads();

    // Phase 2: out[d2][n] = 0.125 * sum_d1 M[d1][d2] * q[n][d1]
    float* out = Yattn + (size_t)g * CC * NN + (size_t)(h*DH) * NN;
    for (int e = tid; e < DH*NN; e += 256) {
        int d2 = e / NN, n = e % NN;
        float a = 0.f;
        #pragma unroll 8
        for (int d1 = 0; d1 < DH; d1++) a = fmaf(Mm[d1*DH + d2], sq[d1*NN + n], a);
        out[(size_t)d2 * NN + n] = a * 0.125f;
    }
}

// ---------------- Launcher ----------------
extern "C" void kernel_launch(void* const* d_in, const int* in_sizes, int n_in,
                              void* d_out, int out_size)
{
    const float* x  = (const float*)d_in[0];
    const float* wq = (const float*)d_in[1];
    const float* sq = (const float*)d_in[2];
    const float* bq = (const float*)d_in[3];
    const float* wk = (const float*)d_in[4];
    const float* sk = (const float*)d_in[5];
    const float* bk = (const float*)d_in[6];
    const float* wv = (const float*)d_in[7];
    const float* sv = (const float*)d_in[8];
    const float* bv = (const float*)d_in[9];
    const float* wp = (const float*)d_in[10];
    const float* sp = (const float*)d_in[11];
    const float* bp = (const float*)d_in[12];
    float* out = (float*)d_out;

    // resolve device-global scratch pointers
    float *Wcat, *scl, *bia, *Yqkv, *Sqkv, *Yattn, *Sattn, *Y2;
    cudaGetSymbolAddress((void**)&Wcat,  g_Wcat);
    cudaGetSymbolAddress((void**)&scl,   g_scale);
    cudaGetSymbolAddress((void**)&bia,   g_bias);
    cudaGetSymbolAddress((void**)&Yqkv,  g_Yqkv);
    cudaGetSymbolAddress((void**)&Sqkv,  g_Sqkv);
    cudaGetSymbolAddress((void**)&Yattn, g_Yattn);
    cudaGetSymbolAddress((void**)&Sattn, g_Sattn);
    cudaGetSymbolAddress((void**)&Y2,    g_Y2);

    // allow 122KB dynamic smem for the attention kernel (idempotent, cheap)
    const int attn_smem = (3*DH*NN + DH*DH) * (int)sizeof(float);  // 122112 B
    cudaFuncSetAttribute(attn_kernel, cudaFuncAttributeMaxDynamicSharedMemorySize, attn_smem);

    // 1) prep concatenated weights/scales/biases
    prep_kernel<<<(CC*CC + 255)/256, 256>>>(wq, wk, wv, sq, bq, sk, bk, sv, bv);

    // 2) QKV conv: [1152x384] @ [384x196] batched over 128, fused BN epilogue
    gemm_bn_kernel<<<dim3(2, C3/BM, GG), GEMM_THREADS>>>(Wcat, x, Yqkv, scl, bia, C3);

    // 3) QKV LIF (v_th = 1.0)
    {
        int per_t = BB * C3 * NN;  // 7,225,344
        lif_kernel<<<(per_t + 255)/256, 256>>>(Yqkv, Sqkv, per_t, 1.0f);
    }

    // 4) factored spiking attention (exact)
    attn_kernel<<<GG * HEADS, 256, attn_smem>>>(Sqkv, Yattn);

    // 5) attn LIF (v_th = 0.5)
    {
        int per_t = BB * CC * NN;  // 2,408,448
        lif_kernel<<<(per_t + 255)/256, 256>>>(Yattn, Sattn, per_t, 0.5f);
    }

    // 6) projection conv: [384x384] @ [384x196] batched, fused BN epilogue
    gemm_bn_kernel<<<dim3(2, CC/BM, GG), GEMM_THREADS>>>(wp, Sattn, Y2, sp, bp, CC);

    // 7) final LIF (v_th = 1.0) straight into d_out
    {
        int per_t = BB * CC * NN;
        lif_kernel<<<(per_t + 255)/256, 256>>>(Y2, out, per_t, 1.0f);
    }
}

// round 5
// speedup vs baseline: 1.5668x; 1.5668x over previous
#include <cuda_runtime.h>
#include <cuda_bf16.h>
#include <cstdint>
#include <cstddef>

// ---------------- Problem constants ----------------
#define TT 4
#define BB 32
#define CC 384
#define NN 196            // H*W
#define GG (TT*BB)        // 128
#define C3 (3*CC)         // 1152
#define HEADS 8
#define DH 48

// ---------------- Scratch (device globals) ----------------
__device__ __align__(16) float g_WcatT[CC*C3];            // [384 k][1152 d]  (q|k|v cols)
__device__ __align__(16) float g_WpT  [CC*CC];            // [384 k][384 d]
__device__ __align__(16) float g_scale[C3];
__device__ __align__(16) float g_bias [C3];
__device__ __align__(16) float g_Sqkv [(size_t)GG*C3*NN]; // QKV spikes (binary floats)
__device__ __align__(16) float g_Sattn[(size_t)GG*CC*NN]; // attn spikes

// ---------------- small PTX helpers ----------------
__device__ __forceinline__ void cp_async16(uint32_t dst, const void* src){
    asm volatile("cp.async.ca.shared.global [%0], [%1], 16;" :: "r"(dst), "l"(src));
}
__device__ __forceinline__ void cp_async8(uint32_t dst, const void* src){
    asm volatile("cp.async.ca.shared.global [%0], [%1], 8;" :: "r"(dst), "l"(src));
}
#define CP_COMMIT() asm volatile("cp.async.commit_group;")
#define CP_WAIT0()  asm volatile("cp.async.wait_group 0;" ::: "memory")

#define FMA2(acc_, a_, b_) asm("fma.rn.f32x2 %0, %1, %2, %0;" : "+l"(acc_) : "l"(a_), "l"(b_))
#define DUP2(dst_, f_) { unsigned _u = __float_as_uint(f_); \
    asm("mov.b64 %0, {%1, %1};" : "=l"(dst_) : "r"(_u)); }
#define UNPK2(lo_, hi_, v_) { unsigned _a, _b; \
    asm("mov.b64 {%0, %1}, %2;" : "=r"(_a), "=r"(_b) : "l"(v_)); \
    lo_ = __uint_as_float(_a); hi_ = __uint_as_float(_b); }

// ---------------- Prep: transpose a 384x384 matrix into dst (stride dstStride) ----
__global__ void transpose384_kernel(const float* __restrict__ src,
                                    float* __restrict__ dst, int dstStride)
{
    __shared__ float tile[32][33];
    int c = blockIdx.x*32 + threadIdx.x;
    int r = blockIdx.y*32 + threadIdx.y;
    tile[threadIdx.y][threadIdx.x] = src[r*CC + c];
    __syncthreads();
    int k = blockIdx.x*32 + threadIdx.y;
    int d = blockIdx.y*32 + threadIdx.x;
    dst[(size_t)k*dstStride + d] = tile[threadIdx.x][threadIdx.y];
}

__global__ void prep_sb_kernel(const float* __restrict__ sq, const float* __restrict__ bq,
                               const float* __restrict__ sk, const float* __restrict__ bk,
                               const float* __restrict__ sv, const float* __restrict__ bv)
{
    int i = threadIdx.x;
    if (i < CC) {
        g_scale[i]        = sq[i];  g_bias[i]        = bq[i];
        g_scale[CC + i]   = sk[i];  g_bias[CC + i]   = bk[i];
        g_scale[2*CC + i] = sv[i];  g_bias[2*CC + i] = bv[i];
    }
}

// ---------------- Fused batched GEMM + BN + multistep LIF --------------------
// AT: [384][M] (k-major weights). B: [128][384][196]. Out: spikes [128][M][196].
// Block computes a BM_ x 98 tile for one b, looping t=0..3 with LIF state in regs.
// f32x2 packed FMA; cp.async double-buffered tiles. Arithmetic is bit-identical
// to the Round-3 kernel (same k-order fp32 FMA chain per element).
template<int BM_, int TM_, int MINB>
__global__ __launch_bounds__(224, MINB)
void gemm_lif_kernel(const float* __restrict__ AT,
                     const float* __restrict__ Bbase,
                     float* __restrict__ Sout,
                     const float* __restrict__ scale,
                     const float* __restrict__ bias,
                     int M, float vth)
{
    constexpr int NACC = TM_/2;
    __shared__ float As[2][16*BM_];
    __shared__ float Bs[2][16*98];

    const int b   = blockIdx.z;
    const int m0  = blockIdx.y * BM_;
    const int n0  = blockIdx.x * 98;
    const int tid = threadIdx.x;
    const int trow = tid / 14;
    const int tcol = tid % 14;
    const int rowoff = trow * TM_;
    const int coloff = tcol * 7;

    const uint32_t sAbase = (uint32_t)__cvta_generic_to_shared(&As[0][0]);
    const uint32_t sBbase = (uint32_t)__cvta_generic_to_shared(&Bs[0][0]);

    float sc[TM_], bi[TM_], vst[TM_][7];
    #pragma unroll
    for (int i = 0; i < TM_; i++) {
        sc[i] = scale[m0 + rowoff + i];
        bi[i] = bias [m0 + rowoff + i];
        #pragma unroll
        for (int j = 0; j < 7; j++) vst[i][j] = 0.f;
    }

#define GL_TILES(ks_, buf_)                                                     \
    {                                                                           \
        const float* Asrc = AT + (size_t)((ks_)*16) * M + m0;                   \
        uint32_t dA = sAbase + (buf_) * (16*BM_*4);                             \
        for (int i = tid; i < 16*(BM_/4); i += 224) {                           \
            int kk = i / (BM_/4), c4 = i % (BM_/4);                             \
            cp_async16(dA + (uint32_t)(kk*BM_ + c4*4)*4,                        \
                       Asrc + (size_t)kk*M + c4*4);                             \
        }                                                                       \
        const float* Bsrc = Bg + (ks_)*16*NN;                                   \
        uint32_t dB = sBbase + (buf_) * (16*98*4);                              \
        for (int i = tid; i < 16*49; i += 224) {                                \
            int kk = i / 49, n2 = i % 49;                                       \
            cp_async8(dB + (uint32_t)(kk*98 + n2*2)*4, Bsrc + kk*NN + n2*2);    \
        }                                                                       \
        CP_COMMIT();                                                            \
    }

    #pragma unroll 1
    for (int t = 0; t < TT; t++) {
        const int g = t*BB + b;
        const float* Bg = Bbase + (size_t)g*CC*NN + n0;

        unsigned long long acc[NACC][7];
        #pragma unroll
        for (int i = 0; i < NACC; i++)
            #pragma unroll
            for (int j = 0; j < 7; j++) acc[i][j] = 0ull;

        GL_TILES(0, 0);
        CP_WAIT0(); __syncthreads();
        int cur = 0;

        #pragma unroll 1
        for (int ks = 0; ks < 24; ks++) {
            if (ks < 23) GL_TILES(ks+1, cur^1);
            #pragma unroll
            for (int kk = 0; kk < 16; kk++) {
                unsigned long long a2[NACC];
                #pragma unroll
                for (int i = 0; i < NACC; i++)
                    a2[i] = *(const unsigned long long*)&As[cur][kk*BM_ + rowoff + 2*i];
                #pragma unroll
                for (int j = 0; j < 7; j++) {
                    unsigned long long b2;
                    DUP2(b2, Bs[cur][kk*98 + coloff + j]);
                    #pragma unroll
                    for (int i = 0; i < NACC; i++)
                        FMA2(acc[i][j], a2[i], b2);
                }
            }
            if (ks < 23) { CP_WAIT0(); __syncthreads(); cur ^= 1; }
        }

        // Epilogue: BN + LIF, write spikes
        float* Sg = Sout + (size_t)g*M*NN + (size_t)m0*NN + n0;
        #pragma unroll
        for (int i2 = 0; i2 < NACC; i2++) {
            #pragma unroll
            for (int j = 0; j < 7; j++) {
                float y0, y1;
                UNPK2(y0, y1, acc[i2][j]);
                {
                    int i = 2*i2;
                    float y = y0 * sc[i] + bi[i];
                    float v = vst[i][j];
                    v = v + (y - v) * 0.5f;
                    float s = (v >= vth) ? 1.f : 0.f;
                    Sg[(size_t)(rowoff + i)*NN + coloff + j] = s;
                    vst[i][j] = v * (1.f - s);
                }
                {
                    int i = 2*i2 + 1;
                    float y = y1 * sc[i] + bi[i];
                    float v = vst[i][j];
                    v = v + (y - v) * 0.5f;
                    float s = (v >= vth) ? 1.f : 0.f;
                    Sg[(size_t)(rowoff + i)*NN + coloff + j] = s;
                    vst[i][j] = v * (1.f - s);
                }
            }
        }
        // buf0 safe to overwrite (all threads synced after ks=22); buf1 readers
        // race only with writes to buf0 of next t, which is a different buffer.
    }
#undef GL_TILES
}

// ---------------- Fused spiking attention + LIF ------------------------------
// Block per (b, head), loops t=0..3 with LIF state in registers.
// Phase 1: M = k^T v via ballot bit-pack + popcount (exact integers).
// Phase 2: out = 0.125 * (M^T q) via f32x2 FMA, then LIF(0.5), write spikes.
#define SQ_ELEMS (DH*NN)        // 9408
#define ATTN_SMEM (SQ_ELEMS*4 + 2*48*9*4 + 48*48*4)  // 50304 B

__global__ __launch_bounds__(256, 2)
void attn_lif_kernel(const float* __restrict__ S, float* __restrict__ Sattn)
{
    extern __shared__ float sm[];
    float*    sq = sm;                       // [48][196]
    unsigned* kb = (unsigned*)(sq + SQ_ELEMS);  // [48][9] (stride 9: no conflicts)
    unsigned* vb = kb + 48*9;
    float*    Mm = (float*)(vb + 48*9);      // [48 d1][48 d2]

    const int b = blockIdx.x >> 3;
    const int h = blockIdx.x & 7;
    const int tid = threadIdx.x;
    const int w = tid >> 5, lane = tid & 31;

    float4 vst[10];
    #pragma unroll
    for (int i = 0; i < 10; i++) vst[i] = make_float4(0.f, 0.f, 0.f, 0.f);

    #pragma unroll 1
    for (int t = 0; t < TT; t++) {
        const int g = t*BB + b;
        const float* base = S + (size_t)g*C3*NN;
        const float* gq = base + (size_t)(        h*DH)*NN;
        const float* gk = base + (size_t)(CC   +  h*DH)*NN;
        const float* gv = base + (size_t)(2*CC +  h*DH)*NN;

        // load q as floats (float4), pack k/v into bitmasks via ballot
        {
            const float4* q4 = (const float4*)gq;
            float4* s4 = (float4*)sq;
            for (int i = tid; i < SQ_ELEMS/4; i += 256) s4[i] = q4[i];
        }
        for (int p = w; p < 48*7; p += 8) {
            int r = p / 7, j = p % 7;
            int m = j*32 + lane;
            float kvv = (m < NN) ? gk[r*NN + m] : 0.f;
            unsigned mk = __ballot_sync(0xffffffffu, kvv > 0.5f);
            float vvv = (m < NN) ? gv[r*NN + m] : 0.f;
            unsigned mv = __ballot_sync(0xffffffffu, vvv > 0.5f);
            if (lane == 0) { kb[r*9 + j] = mk; vb[r*9 + j] = mv; }
        }
        __syncthreads();

        // Phase 1: Mm[d1*48+d2] = popcount(k_bits[d1] & v_bits[d2])
        for (int e = tid; e < 48*48; e += 256) {
            int d1 = e / 48, d2 = e % 48;
            const unsigned* kr = kb + d1*9;
            const unsigned* vr = vb + d2*9;
            int cnt = 0;
            #pragma unroll
            for (int j = 0; j < 7; j++) cnt += __popc(kr[j] & vr[j]);
            Mm[e] = (float)cnt;
        }
        __syncthreads();

        // Phase 2 + LIF: out[d2][n0..n0+3]
        float* So = Sattn + (size_t)g*CC*NN + (size_t)(h*DH)*NN;
        #pragma unroll
        for (int it = 0; it < 10; it++) {
            int tau = tid + it*256;
            if (tau < 48*49) {
                int d2 = tau / 49, n0 = (tau % 49)*4;
                unsigned long long a0 = 0ull, a1 = 0ull;
                #pragma unroll 4
                for (int d1 = 0; d1 < 48; d1++) {
                    unsigned long long m2;
                    DUP2(m2, Mm[d1*48 + d2]);
                    ulonglong2 q2 = *(const ulonglong2*)(sq + d1*NN + n0);
                    FMA2(a0, q2.x, m2);
                    FMA2(a1, q2.y, m2);
                }
                float y0, y1, y2, y3;
                UNPK2(y0, y1, a0);
                UNPK2(y2, y3, a1);
                float4 v4 = vst[it], s4;
                {   float y = y0*0.125f; float v = v4.x; v = v + (y - v)*0.5f;
                    float s = (v >= 0.5f) ? 1.f : 0.f; s4.x = s; v4.x = v*(1.f - s); }
                {   float y = y1*0.125f; float v = v4.y; v = v + (y - v)*0.5f;
                    float s = (v >= 0.5f) ? 1.f : 0.f; s4.y = s; v4.y = v*(1.f - s); }
                {   float y = y2*0.125f; float v = v4.z; v = v + (y - v)*0.5f;
                    float s = (v >= 0.5f) ? 1.f : 0.f; s4.z = s; v4.z = v*(1.f - s); }
                {   float y = y3*0.125f; float v = v4.w; v = v + (y - v)*0.5f;
                    float s = (v >= 0.5f) ? 1.f : 0.f; s4.w = s; v4.w = v*(1.f - s); }
                vst[it] = v4;
                *(float4*)(So + (size_t)d2*NN + n0) = s4;
            }
        }
        __syncthreads();   // protect sq/kb/vb/Mm before next t overwrites
    }
}

// ---------------- Launcher ----------------
extern "C" void kernel_launch(void* const* d_in, const int* in_sizes, int n_in,
                              void* d_out, int out_size)
{
    const float* x  = (const float*)d_in[0];
    const float* wq = (const float*)d_in[1];
    const float* sq = (const float*)d_in[2];
    const float* bq = (const float*)d_in[3];
    const float* wk = (const float*)d_in[4];
    const float* sk = (const float*)d_in[5];
    const float* bk = (const float*)d_in[6];
    const float* wv = (const float*)d_in[7];
    const float* sv = (const float*)d_in[8];
    const float* bv = (const float*)d_in[9];
    const float* wp = (const float*)d_in[10];
    const float* sp = (const float*)d_in[11];
    const float* bp = (const float*)d_in[12];
    float* out = (float*)d_out;

    float *WcatT, *WpT, *scl, *bia, *Sqkv, *Sattn;
    cudaGetSymbolAddress((void**)&WcatT, g_WcatT);
    cudaGetSymbolAddress((void**)&WpT,   g_WpT);
    cudaGetSymbolAddress((void**)&scl,   g_scale);
    cudaGetSymbolAddress((void**)&bia,   g_bias);
    cudaGetSymbolAddress((void**)&Sqkv,  g_Sqkv);
    cudaGetSymbolAddress((void**)&Sattn, g_Sattn);

    cudaFuncSetAttribute(attn_lif_kernel,
                         cudaFuncAttributeMaxDynamicSharedMemorySize, ATTN_SMEM);

    // prep: transposed weights (k-major) + concatenated scale/bias
    dim3 tgrid(12, 12), tblk(32, 32);
    transpose384_kernel<<<tgrid, tblk>>>(wq, WcatT + 0,      C3);
    transpose384_kernel<<<tgrid, tblk>>>(wk, WcatT + CC,     C3);
    transpose384_kernel<<<tgrid, tblk>>>(wv, WcatT + 2*CC,   C3);
    transpose384_kernel<<<tgrid, tblk>>>(wp, WpT,            CC);
    prep_sb_kernel<<<1, CC>>>(sq, bq, sk, bk, sv, bv);

    // QKV conv+BN+LIF fused (writes binary spikes only)
    gemm_lif_kernel<128, 8, 1><<<dim3(2, C3/128, BB), 224>>>(
        WcatT, x, Sqkv, scl, bia, C3, 1.0f);

    // spiking attention + attn-LIF fused
    attn_lif_kernel<<<BB*HEADS, 256, ATTN_SMEM>>>(Sqkv, Sattn);

    // projection conv+BN+LIF fused, writes final spikes straight to d_out
    gemm_lif_kernel<64, 4, 2><<<dim3(2, CC/64, BB), 224>>>(
        WpT, Sattn, out, sp, bp, CC, 1.0f);
}